// round 12
// baseline (speedup 1.0000x reference)
#include <cuda_runtime.h>
#include <cstdint>

#define N_NODES 100000
#define N_EDGES 1600000
#define BN_EPS  1e-5f
#define CAP     64          // padded-CSR bucket capacity (max in-degree ~40)
#define CAPSH   6
#define NBANK   32          // replicated BN-stat banks (atomic de-serialization)

// ---------------- scratch (static __device__, no allocations) ----------------
__device__ int    g_count[N_NODES];         // in-degree, built by scatter
__device__ int    g_col[N_NODES * CAP];     // padded CSR: sources per dst
__device__ float  g_dinv[N_NODES];
__device__ float4 g_b0[N_NODES * 12];       // gather-input rows (max 48 floats)
__device__ float4 g_b1[N_NODES * 12];       // agg buffer (max 48 floats)
__device__ float4 g_b2[N_NODES * 16];       // wide buffer (max 64 floats)
__device__ float  g_bnpart[3][NBANK][128];  // per-layer banked stats: [f]=sum,[64+f]=sq
__device__ float  g_bna[64];
__device__ float  g_bnc[64];

template<int B> __device__ __forceinline__ float4* buf4() {
    if (B == 0) return g_b0;
    if (B == 1) return g_b1;
    return g_b2;
}
template<int B> __device__ __forceinline__ float* buff() {
    return (float*)buf4<B>();
}

// ------- padded-CSR scatter: pos = old count; col[dst*CAP+pos] = src --------
__global__ void k_scatter(const int* __restrict__ ei) {
    int t = blockIdx.x * blockDim.x + threadIdx.x;
    if (t < N_EDGES / 2) {
        int2 s2 = reinterpret_cast<const int2*>(ei)[t];
        int2 d2 = reinterpret_cast<const int2*>(ei + N_EDGES)[t];
        int p0 = atomicAdd(&g_count[d2.x], 1);
        if (p0 < CAP) g_col[(d2.x << CAPSH) + p0] = s2.x;
        int p1 = atomicAdd(&g_count[d2.y], 1);
        if (p1 < CAP) g_col[(d2.y << CAPSH) + p1] = s2.y;
    }
}

// ------- prep: dinv = rsqrt(deg+1); b0 rows = dinv*x padded 20->32 ----------
__global__ void k_prep(const float* __restrict__ x) {
    int i = blockIdx.x * blockDim.x + threadIdx.x;
    if (i < N_NODES) {
        float d = rsqrtf((float)g_count[i] + 1.0f);
        g_dinv[i] = d;
        float4* row = g_b0 + i * 8;
        #pragma unroll
        for (int c = 0; c < 8; c++) {
            float4 o;
            o.x = (4 * c     < 20) ? x[i * 20 + 4 * c]     * d : 0.f;
            o.y = (4 * c + 1 < 20) ? x[i * 20 + 4 * c + 1] * d : 0.f;
            o.z = (4 * c + 2 < 20) ? x[i * 20 + 4 * c + 2] * d : 0.f;
            o.w = (4 * c + 3 < 20) ? x[i * 20 + 4 * c + 3] * d : 0.f;
            row[c] = o;
        }
    }
}

// ------- dual-node gather-aggregate: out[i]=dinv[i]*(self+sum p[src]) -------
// STATS >= 0: accumulate per-feature sum/sq into banked g_bnpart[STATS].
template<int FPAD, int EPW, int PB, int OB, int STATS>
__global__ void k_gather() {
    constexpr int LW = FPAD / 4;
    constexpr bool ST = (STATS >= 0);
    constexpr int LIDX = ST ? STATS : 0;
    const float4* __restrict__ p4 = buf4<PB>();
    float4* __restrict__ o4 = buf4<OB>();
    __shared__ float bsum[ST ? FPAD : 1];
    __shared__ float bsq[ST ? FPAD : 1];
    const int tid = threadIdx.x;
    const int lane = tid & 31;
    const int grp = lane / LW;
    const int c   = lane % LW;
    const bool active = grp < EPW;
    if (ST) {
        for (int i = tid; i < FPAD; i += blockDim.x) { bsum[i] = 0.f; bsq[i] = 0.f; }
        __syncthreads();
    }
    int warp = (blockIdx.x * blockDim.x + tid) >> 5;
    const int nwarps = (gridDim.x * blockDim.x) >> 5;
    float4 s4 = {0.f, 0.f, 0.f, 0.f}, q4 = {0.f, 0.f, 0.f, 0.f};
    for (int i0 = warp * 2; i0 < N_NODES; i0 += nwarps * 2) {
        const int i1 = i0 + 1;                    // N_NODES even -> always valid
        const int cntA = min(g_count[i0], CAP);
        const int cntB = min(g_count[i1], CAP);
        const int begA = i0 << CAPSH, begB = i1 << CAPSH;
        float4 accA = {0.f, 0.f, 0.f, 0.f}, accB = {0.f, 0.f, 0.f, 0.f};
        if (grp == 0) { accA = p4[i0 * LW + c]; accB = p4[i1 * LW + c]; }
        const int mx = max(cntA, cntB);
        for (int j = grp; j < mx; j += EPW) {
            if (active && j < cntA) {
                int idx = g_col[begA + j];
                float4 v = p4[idx * LW + c];
                accA.x += v.x; accA.y += v.y; accA.z += v.z; accA.w += v.w;
            }
            if (active && j < cntB) {
                int idx = g_col[begB + j];
                float4 v = p4[idx * LW + c];
                accB.x += v.x; accB.y += v.y; accB.z += v.z; accB.w += v.w;
            }
        }
        if (LW == 8) {
            #pragma unroll
            for (int off = 8; off < 32; off <<= 1) {
                accA.x += __shfl_xor_sync(0xffffffffu, accA.x, off);
                accA.y += __shfl_xor_sync(0xffffffffu, accA.y, off);
                accA.z += __shfl_xor_sync(0xffffffffu, accA.z, off);
                accA.w += __shfl_xor_sync(0xffffffffu, accA.w, off);
                accB.x += __shfl_xor_sync(0xffffffffu, accB.x, off);
                accB.y += __shfl_xor_sync(0xffffffffu, accB.y, off);
                accB.z += __shfl_xor_sync(0xffffffffu, accB.z, off);
                accB.w += __shfl_xor_sync(0xffffffffu, accB.w, off);
            }
        } else {                        // LW == 12, EPW == 2: slot1 -> slot0
            accA.x += __shfl_down_sync(0xffffffffu, accA.x, 12);
            accA.y += __shfl_down_sync(0xffffffffu, accA.y, 12);
            accA.z += __shfl_down_sync(0xffffffffu, accA.z, 12);
            accA.w += __shfl_down_sync(0xffffffffu, accA.w, 12);
            accB.x += __shfl_down_sync(0xffffffffu, accB.x, 12);
            accB.y += __shfl_down_sync(0xffffffffu, accB.y, 12);
            accB.z += __shfl_down_sync(0xffffffffu, accB.z, 12);
            accB.w += __shfl_down_sync(0xffffffffu, accB.w, 12);
        }
        if (grp == 0) {
            float dA = g_dinv[i0], dB = g_dinv[i1];
            float4 oA = {dA * accA.x, dA * accA.y, dA * accA.z, dA * accA.w};
            float4 oB = {dB * accB.x, dB * accB.y, dB * accB.z, dB * accB.w};
            o4[i0 * LW + c] = oA;
            o4[i1 * LW + c] = oB;
            if (ST) {
                s4.x += oA.x + oB.x; s4.y += oA.y + oB.y;
                s4.z += oA.z + oB.z; s4.w += oA.w + oB.w;
                q4.x += oA.x * oA.x + oB.x * oB.x;
                q4.y += oA.y * oA.y + oB.y * oB.y;
                q4.z += oA.z * oA.z + oB.z * oB.z;
                q4.w += oA.w * oA.w + oB.w * oB.w;
            }
        }
    }
    if (ST) {
        if (grp == 0) {
            atomicAdd(&bsum[c * 4 + 0], s4.x); atomicAdd(&bsq[c * 4 + 0], q4.x);
            atomicAdd(&bsum[c * 4 + 1], s4.y); atomicAdd(&bsq[c * 4 + 1], q4.y);
            atomicAdd(&bsum[c * 4 + 2], s4.z); atomicAdd(&bsq[c * 4 + 2], q4.z);
            atomicAdd(&bsum[c * 4 + 3], s4.w); atomicAdd(&bsq[c * 4 + 3], q4.w);
        }
        __syncthreads();
        float* bank = g_bnpart[LIDX][blockIdx.x & (NBANK - 1)];
        for (int i = tid; i < FPAD; i += blockDim.x) {
            atomicAdd(&bank[i],      bsum[i]);
            atomicAdd(&bank[64 + i], bsq[i]);
        }
    }
}

// ------ register-tiled GEMM, float4 input loads; banked BN stats ------------
template<int FIN, int IS, int FOUT, int NC, int NG, int NT,
         bool BN_IN, bool DINV_OUT, int IB, int OB, int STATS>
__global__ void k_gemm(const float* __restrict__ W) {
    constexpr int NO   = 4;
    constexpr int NPB  = NG * NT;
    constexpr int SPAD = FIN + 4;           // keeps 16B alignment (FIN%4==0)
    constexpr bool ST = (STATS >= 0);
    constexpr int LIDX = ST ? STATS : 0;
    const float* __restrict__ in = buff<IB>();
    float* __restrict__ out = buff<OB>();
    __shared__ float sW[FIN * FOUT];
    __shared__ float sIn[NPB * SPAD];
    __shared__ float bsum[ST ? FOUT : 1];
    __shared__ float bsq[ST ? FOUT : 1];
    const int tid = threadIdx.x;
    const int nthreads = NC * NG;
    for (int idx = tid; idx < FIN * FOUT / 4; idx += nthreads)
        reinterpret_cast<float4*>(sW)[idx] = reinterpret_cast<const float4*>(W)[idx];
    if (ST) {
        for (int i = tid; i < FOUT; i += nthreads) { bsum[i] = 0.f; bsq[i] = 0.f; }
    }
    const int co = tid % NC;
    const int g  = tid / NC;
    float s[NO], q[NO];
    #pragma unroll
    for (int o = 0; o < NO; o++) { s[o] = 0.f; q[o] = 0.f; }
    for (int base = blockIdx.x * NPB; base < N_NODES; base += gridDim.x * NPB) {
        __syncthreads();
        for (int idx = tid; idx < NPB * (FIN / 4); idx += nthreads) {
            int nl = idx / (FIN / 4), k4 = idx - nl * (FIN / 4);
            int node = base + nl;
            float4 v = {0.f, 0.f, 0.f, 0.f};
            if (node < N_NODES) {
                v = *reinterpret_cast<const float4*>(&in[node * IS + k4 * 4]);
                if (BN_IN) {
                    int k = k4 * 4;
                    v.x = fmaxf(fmaf(v.x, g_bna[k],     g_bnc[k]),     0.f);
                    v.y = fmaxf(fmaf(v.y, g_bna[k + 1], g_bnc[k + 1]), 0.f);
                    v.z = fmaxf(fmaf(v.z, g_bna[k + 2], g_bnc[k + 2]), 0.f);
                    v.w = fmaxf(fmaf(v.w, g_bna[k + 3], g_bnc[k + 3]), 0.f);
                }
            }
            *reinterpret_cast<float4*>(&sIn[nl * SPAD + k4 * 4]) = v;
        }
        __syncthreads();
        float acc[NT][NO];
        #pragma unroll
        for (int j = 0; j < NT; j++)
            #pragma unroll
            for (int o = 0; o < NO; o++) acc[j][o] = 0.f;
        #pragma unroll 2
        for (int k4 = 0; k4 < FIN / 4; k4++) {
            float4 a[NT];
            #pragma unroll
            for (int j = 0; j < NT; j++)
                a[j] = *reinterpret_cast<const float4*>(
                    &sIn[(g * NT + j) * SPAD + k4 * 4]);
            #pragma unroll
            for (int kk = 0; kk < 4; kk++) {
                float4 w = *reinterpret_cast<const float4*>(
                    &sW[(k4 * 4 + kk) * FOUT + co * NO]);
                #pragma unroll
                for (int j = 0; j < NT; j++) {
                    float av = (kk == 0) ? a[j].x : (kk == 1) ? a[j].y
                             : (kk == 2) ? a[j].z : a[j].w;
                    acc[j][0] = fmaf(av, w.x, acc[j][0]);
                    acc[j][1] = fmaf(av, w.y, acc[j][1]);
                    acc[j][2] = fmaf(av, w.z, acc[j][2]);
                    acc[j][3] = fmaf(av, w.w, acc[j][3]);
                }
            }
        }
        #pragma unroll
        for (int j = 0; j < NT; j++) {
            int node = base + g * NT + j;
            if (node < N_NODES) {
                float d = DINV_OUT ? g_dinv[node] : 1.f;
                float4 o = {acc[j][0] * d, acc[j][1] * d, acc[j][2] * d, acc[j][3] * d};
                *reinterpret_cast<float4*>(&out[node * FOUT + co * NO]) = o;
                if (ST) {
                    s[0] += o.x; q[0] += o.x * o.x;
                    s[1] += o.y; q[1] += o.y * o.y;
                    s[2] += o.z; q[2] += o.z * o.z;
                    s[3] += o.w; q[3] += o.w * o.w;
                }
            }
        }
    }
    if (ST) {
        #pragma unroll
        for (int o = 0; o < NO; o++) {
            atomicAdd(&bsum[co * NO + o], s[o]);
            atomicAdd(&bsq[co * NO + o], q[o]);
        }
        __syncthreads();
        float* bank = g_bnpart[LIDX][blockIdx.x & (NBANK - 1)];
        for (int i = tid; i < FOUT; i += nthreads) {
            atomicAdd(&bank[i],      bsum[i]);
            atomicAdd(&bank[64 + i], bsq[i]);
        }
    }
}

// ------- BN params from banked partials: a = g*rsqrt(var+eps), c = beta-mu*a -
template<int F, int LIDX>
__global__ void k_bnparam(const float* __restrict__ g, const float* __restrict__ beta) {
    int f = threadIdx.x;
    if (f < F) {
        float sum = 0.f, sq = 0.f;
        #pragma unroll
        for (int b = 0; b < NBANK; b++) {
            sum += g_bnpart[LIDX][b][f];
            sq  += g_bnpart[LIDX][b][64 + f];
        }
        float inv_n = 1.0f / (float)N_NODES;
        float mu  = sum * inv_n;
        float var = sq * inv_n - mu * mu;
        float a = g[f] * rsqrtf(var + BN_EPS);
        g_bna[f] = a;
        g_bnc[f] = beta[f] - mu * a;
    }
}

// ---------------- final apply (no ReLU): out = bn(b2 stride 32) --------------
__global__ void k_apply(float* __restrict__ out) {
    int idx = blockIdx.x * blockDim.x + threadIdx.x;
    const int total = N_NODES * 32;
    if (idx < total) {
        int f = idx & 31;
        out[idx] = fmaf(((const float*)g_b2)[idx], g_bna[f], g_bnc[f]);
    }
}

// ---------------- launcher ----------------
extern "C" void kernel_launch(void* const* d_in, const int* in_sizes, int n_in,
                              void* d_out, int out_size) {
    const float* x   = (const float*)d_in[0];
    const int*   ei  = (const int*)d_in[1];          // int32
    const float* W1  = (const float*)d_in[2];
    const float* g1  = (const float*)d_in[4];
    const float* be1 = (const float*)d_in[5];
    const float* W2  = (const float*)d_in[6];
    const float* g2  = (const float*)d_in[8];
    const float* be2 = (const float*)d_in[9];
    const float* W3  = (const float*)d_in[10];
    const float* g3  = (const float*)d_in[12];
    const float* be3 = (const float*)d_in[13];
    float* out = (float*)d_out;

    // zero per-call state (memset nodes, not kernel launches)
    void* pa;
    cudaGetSymbolAddress(&pa, g_count);
    cudaMemsetAsync(pa, 0, sizeof(int) * N_NODES);
    cudaGetSymbolAddress(&pa, g_bnpart);
    cudaMemsetAsync(pa, 0, sizeof(float) * 3 * NBANK * 128);

    // ---- padded-CSR build + prep ----
    k_scatter<<<(N_EDGES / 2 + 255) / 256, 256>>>(ei);        // 0
    k_prep<<<(N_NODES + 255) / 256, 256>>>(x);                // 1

    // ---- layer 1 ----
    k_gather<32, 4, 0, 1, -1><<<2048, 256>>>();               // 2: b0 -> b1
    k_gemm<20, 32, 64, 16, 16, 4, false, false, 1, 2, 0>
        <<<(N_NODES + 63) / 64, 256>>>(W1);                   // 3 <- PROFILED: b1 -> b2
    k_bnparam<64, 0><<<1, 64>>>(g1, be1);                     // 4

    // ---- layer 2 ----
    k_gemm<64, 64, 48, 12, 20, 4, true, true, 2, 0, -1>
        <<<(N_NODES + 79) / 80, 240>>>(W2);                   // 5: b2 -> b0
    k_gather<48, 2, 0, 1, 1><<<2048, 256>>>();                // 6: b0 -> b1 (+BN2 stats)
    k_bnparam<48, 1><<<1, 64>>>(g2, be2);                     // 7

    // ---- layer 3 ----
    k_gemm<48, 48, 32, 8, 32, 4, true, true, 1, 0, -1>
        <<<(N_NODES + 127) / 128, 256>>>(W3);                 // 8: b1 -> b0
    k_gather<32, 4, 0, 2, 2><<<2048, 256>>>();                // 9: b0 -> b2 (+BN3 stats)
    k_bnparam<32, 2><<<1, 64>>>(g3, be3);                     // 10

    // ---- final BN apply ----
    k_apply<<<(N_NODES * 32 + 255) / 256, 256>>>(out);        // 11
}

// round 14
// speedup vs baseline: 1.0598x; 1.0598x over previous
#include <cuda_runtime.h>
#include <cstdint>

#define N_NODES 100000
#define N_EDGES 1600000
#define BN_EPS  1e-5f
#define CAP     64          // padded-CSR bucket capacity (max in-degree ~40)
#define CAPSH   6
#define NBANK   8           // replicated BN-stat banks

// ---------------- scratch (static __device__, no allocations) ----------------
__device__ int    g_count[N_NODES];         // in-degree, built by scatter
__device__ int    g_col[N_NODES * CAP];     // padded CSR: sources per dst
__device__ float  g_dinv[N_NODES];
__device__ float4 g_b0[N_NODES * 12];       // rows: L1 in (20f) / p2 (48f) / p3 (32f)
__device__ float4 g_b1[N_NODES * 12];       // agg2 (48f)
__device__ float4 g_b2[N_NODES * 16];       // h1 (64f) / agg3 (32f)
__device__ float  g_bnpart[3][NBANK][128];  // banked stats: [f]=sum, [64+f]=sumsq

template<int B> __device__ __forceinline__ float4* buf4() {
    if (B == 0) return g_b0;
    if (B == 1) return g_b1;
    return g_b2;
}
template<int B> __device__ __forceinline__ float* buff() {
    return (float*)buf4<B>();
}

// ------- padded-CSR scatter: pos = old count; col[dst*CAP+pos] = src --------
__global__ void k_scatter(const int* __restrict__ ei) {
    int t = blockIdx.x * blockDim.x + threadIdx.x;
    if (t < N_EDGES / 2) {
        int2 s2 = reinterpret_cast<const int2*>(ei)[t];
        int2 d2 = reinterpret_cast<const int2*>(ei + N_EDGES)[t];
        int p0 = atomicAdd(&g_count[d2.x], 1);
        if (p0 < CAP) g_col[(d2.x << CAPSH) + p0] = s2.x;
        int p1 = atomicAdd(&g_count[d2.y], 1);
        if (p1 < CAP) g_col[(d2.y << CAPSH) + p1] = s2.y;
    }
}

// ------- prep: dinv = rsqrt(deg+1); b0 rows (20 floats) = dinv .* x ---------
__global__ void k_prep(const float* __restrict__ x) {
    int i = blockIdx.x * blockDim.x + threadIdx.x;
    if (i < N_NODES) {
        float d = rsqrtf((float)g_count[i] + 1.0f);
        g_dinv[i] = d;
        const float4* xr = reinterpret_cast<const float4*>(x) + i * 5;
        float4* row = g_b0 + i * 5;
        #pragma unroll
        for (int c = 0; c < 5; c++) {
            float4 v = xr[c];
            v.x *= d; v.y *= d; v.z *= d; v.w *= d;
            row[c] = v;
        }
    }
}

// ------- fused layer 1: gather(20f) + GEMM 20->64 (reg weights) + BN1 stats --
// Dual-node per warp. LW=5 lanes/edge (80B rows), EPW=6. Reduction via guarded
// shfl_down 5/10/20 (out-of-range shfl returns OWN value -> must predicate the
// add with lane+d<32, else lanes 22-24 self-double at d=10).
__global__ void k_layer1(const float* __restrict__ W1) {
    const int tid = threadIdx.x, lane = tid & 31;
    float w_lo[20], w_hi[20];
    #pragma unroll
    for (int k = 0; k < 20; k++) {
        w_lo[k] = W1[k * 64 + lane];
        w_hi[k] = W1[k * 64 + 32 + lane];
    }
    __shared__ float bsum[64];
    __shared__ float bsq[64];
    for (int i = tid; i < 64; i += blockDim.x) { bsum[i] = 0.f; bsq[i] = 0.f; }
    __syncthreads();
    const int grp = lane / 5;          // 0..6 (grp 6 = lanes 30,31 inactive)
    const int c   = lane % 5;
    const bool active = grp < 6;
    const float4* __restrict__ p4 = g_b0;
    float* __restrict__ h = (float*)g_b2;
    int warp = (blockIdx.x * blockDim.x + tid) >> 5;
    const int nwarps = (gridDim.x * blockDim.x) >> 5;
    float s_lo = 0.f, q_lo = 0.f, s_hi = 0.f, q_hi = 0.f;
    for (int i0 = warp * 2; i0 < N_NODES; i0 += nwarps * 2) {
        const int i1 = i0 + 1;                   // N_NODES even
        const int cntA = min(g_count[i0], CAP);
        const int cntB = min(g_count[i1], CAP);
        const int begA = i0 << CAPSH, begB = i1 << CAPSH;
        float4 accA = {0.f, 0.f, 0.f, 0.f}, accB = {0.f, 0.f, 0.f, 0.f};
        if (grp == 0) { accA = p4[i0 * 5 + c]; accB = p4[i1 * 5 + c]; }
        const int mx = max(cntA, cntB);
        for (int j = grp; j < mx; j += 6) {
            if (active && j < cntA) {
                int idx = g_col[begA + j];
                float4 v = p4[idx * 5 + c];
                accA.x += v.x; accA.y += v.y; accA.z += v.z; accA.w += v.w;
            }
            if (active && j < cntB) {
                int idx = g_col[begB + j];
                float4 v = p4[idx * 5 + c];
                accB.x += v.x; accB.y += v.y; accB.z += v.z; accB.w += v.w;
            }
        }
        // guarded reduction: slots at lanes 0,5,10,15,20,25
        #pragma unroll
        for (int d = 5; d <= 20; d <<= 1) {     // d = 5, 10, 20
            float tax = __shfl_down_sync(0xffffffffu, accA.x, d);
            float tay = __shfl_down_sync(0xffffffffu, accA.y, d);
            float taz = __shfl_down_sync(0xffffffffu, accA.z, d);
            float taw = __shfl_down_sync(0xffffffffu, accA.w, d);
            float tbx = __shfl_down_sync(0xffffffffu, accB.x, d);
            float tby = __shfl_down_sync(0xffffffffu, accB.y, d);
            float tbz = __shfl_down_sync(0xffffffffu, accB.z, d);
            float tbw = __shfl_down_sync(0xffffffffu, accB.w, d);
            if (lane + d < 32) {
                accA.x += tax; accA.y += tay; accA.z += taz; accA.w += taw;
                accB.x += tbx; accB.y += tby; accB.z += tbz; accB.w += tbw;
            }
        }
        // lanes 0..4 hold the aggregated 20-float rows; broadcast + GEMM
        float oA0 = 0.f, oA1 = 0.f, oB0 = 0.f, oB1 = 0.f;
        #pragma unroll
        for (int k4 = 0; k4 < 5; k4++) {
            float ax = __shfl_sync(0xffffffffu, accA.x, k4);
            float ay = __shfl_sync(0xffffffffu, accA.y, k4);
            float az = __shfl_sync(0xffffffffu, accA.z, k4);
            float aw = __shfl_sync(0xffffffffu, accA.w, k4);
            float bx = __shfl_sync(0xffffffffu, accB.x, k4);
            float by = __shfl_sync(0xffffffffu, accB.y, k4);
            float bz = __shfl_sync(0xffffffffu, accB.z, k4);
            float bw = __shfl_sync(0xffffffffu, accB.w, k4);
            int k = k4 * 4;
            oA0 = fmaf(ax, w_lo[k],     oA0); oA1 = fmaf(ax, w_hi[k],     oA1);
            oA0 = fmaf(ay, w_lo[k + 1], oA0); oA1 = fmaf(ay, w_hi[k + 1], oA1);
            oA0 = fmaf(az, w_lo[k + 2], oA0); oA1 = fmaf(az, w_hi[k + 2], oA1);
            oA0 = fmaf(aw, w_lo[k + 3], oA0); oA1 = fmaf(aw, w_hi[k + 3], oA1);
            oB0 = fmaf(bx, w_lo[k],     oB0); oB1 = fmaf(bx, w_hi[k],     oB1);
            oB0 = fmaf(by, w_lo[k + 1], oB0); oB1 = fmaf(by, w_hi[k + 1], oB1);
            oB0 = fmaf(bz, w_lo[k + 2], oB0); oB1 = fmaf(bz, w_hi[k + 2], oB1);
            oB0 = fmaf(bw, w_lo[k + 3], oB0); oB1 = fmaf(bw, w_hi[k + 3], oB1);
        }
        float dA = g_dinv[i0], dB = g_dinv[i1];
        oA0 *= dA; oA1 *= dA; oB0 *= dB; oB1 *= dB;
        h[i0 * 64 + lane]      = oA0;
        h[i0 * 64 + 32 + lane] = oA1;
        h[i1 * 64 + lane]      = oB0;
        h[i1 * 64 + 32 + lane] = oB1;
        s_lo += oA0 + oB0; q_lo += oA0 * oA0 + oB0 * oB0;
        s_hi += oA1 + oB1; q_hi += oA1 * oA1 + oB1 * oB1;
    }
    atomicAdd(&bsum[lane], s_lo);      atomicAdd(&bsq[lane], q_lo);
    atomicAdd(&bsum[32 + lane], s_hi); atomicAdd(&bsq[32 + lane], q_hi);
    __syncthreads();
    float* bank = g_bnpart[0][blockIdx.x & (NBANK - 1)];
    for (int i = tid; i < 64; i += blockDim.x) {
        atomicAdd(&bank[i],      bsum[i]);
        atomicAdd(&bank[64 + i], bsq[i]);
    }
}

// ------- dual-node gather-aggregate: out[i]=dinv[i]*(self+sum p[src]) -------
// STATS >= 0: accumulate per-feature sum/sq into banked g_bnpart[STATS].
template<int FPAD, int EPW, int PB, int OB, int STATS>
__global__ void k_gather() {
    constexpr int LW = FPAD / 4;
    constexpr bool ST = (STATS >= 0);
    constexpr int LIDX = ST ? STATS : 0;
    const float4* __restrict__ p4 = buf4<PB>();
    float4* __restrict__ o4 = buf4<OB>();
    __shared__ float bsum[ST ? FPAD : 1];
    __shared__ float bsq[ST ? FPAD : 1];
    const int tid = threadIdx.x;
    const int lane = tid & 31;
    const int grp = lane / LW;
    const int c   = lane % LW;
    const bool active = grp < EPW;
    if (ST) {
        for (int i = tid; i < FPAD; i += blockDim.x) { bsum[i] = 0.f; bsq[i] = 0.f; }
        __syncthreads();
    }
    int warp = (blockIdx.x * blockDim.x + tid) >> 5;
    const int nwarps = (gridDim.x * blockDim.x) >> 5;
    float4 s4 = {0.f, 0.f, 0.f, 0.f}, q4 = {0.f, 0.f, 0.f, 0.f};
    for (int i0 = warp * 2; i0 < N_NODES; i0 += nwarps * 2) {
        const int i1 = i0 + 1;
        const int cntA = min(g_count[i0], CAP);
        const int cntB = min(g_count[i1], CAP);
        const int begA = i0 << CAPSH, begB = i1 << CAPSH;
        float4 accA = {0.f, 0.f, 0.f, 0.f}, accB = {0.f, 0.f, 0.f, 0.f};
        if (grp == 0) { accA = p4[i0 * LW + c]; accB = p4[i1 * LW + c]; }
        const int mx = max(cntA, cntB);
        for (int j = grp; j < mx; j += EPW) {
            if (active && j < cntA) {
                int idx = g_col[begA + j];
                float4 v = p4[idx * LW + c];
                accA.x += v.x; accA.y += v.y; accA.z += v.z; accA.w += v.w;
            }
            if (active && j < cntB) {
                int idx = g_col[begB + j];
                float4 v = p4[idx * LW + c];
                accB.x += v.x; accB.y += v.y; accB.z += v.z; accB.w += v.w;
            }
        }
        if (LW == 8) {
            #pragma unroll
            for (int off = 8; off < 32; off <<= 1) {
                accA.x += __shfl_xor_sync(0xffffffffu, accA.x, off);
                accA.y += __shfl_xor_sync(0xffffffffu, accA.y, off);
                accA.z += __shfl_xor_sync(0xffffffffu, accA.z, off);
                accA.w += __shfl_xor_sync(0xffffffffu, accA.w, off);
                accB.x += __shfl_xor_sync(0xffffffffu, accB.x, off);
                accB.y += __shfl_xor_sync(0xffffffffu, accB.y, off);
                accB.z += __shfl_xor_sync(0xffffffffu, accB.z, off);
                accB.w += __shfl_xor_sync(0xffffffffu, accB.w, off);
            }
        } else {                        // LW == 12, EPW == 2: slot1 -> slot0
            accA.x += __shfl_down_sync(0xffffffffu, accA.x, 12);
            accA.y += __shfl_down_sync(0xffffffffu, accA.y, 12);
            accA.z += __shfl_down_sync(0xffffffffu, accA.z, 12);
            accA.w += __shfl_down_sync(0xffffffffu, accA.w, 12);
            accB.x += __shfl_down_sync(0xffffffffu, accB.x, 12);
            accB.y += __shfl_down_sync(0xffffffffu, accB.y, 12);
            accB.z += __shfl_down_sync(0xffffffffu, accB.z, 12);
            accB.w += __shfl_down_sync(0xffffffffu, accB.w, 12);
        }
        if (grp == 0) {
            float dA = g_dinv[i0], dB = g_dinv[i1];
            float4 oA = {dA * accA.x, dA * accA.y, dA * accA.z, dA * accA.w};
            float4 oB = {dB * accB.x, dB * accB.y, dB * accB.z, dB * accB.w};
            o4[i0 * LW + c] = oA;
            o4[i1 * LW + c] = oB;
            if (ST) {
                s4.x += oA.x + oB.x; s4.y += oA.y + oB.y;
                s4.z += oA.z + oB.z; s4.w += oA.w + oB.w;
                q4.x += oA.x * oA.x + oB.x * oB.x;
                q4.y += oA.y * oA.y + oB.y * oB.y;
                q4.z += oA.z * oA.z + oB.z * oB.z;
                q4.w += oA.w * oA.w + oB.w * oB.w;
            }
        }
    }
    if (ST) {
        if (grp == 0) {
            atomicAdd(&bsum[c * 4 + 0], s4.x); atomicAdd(&bsq[c * 4 + 0], q4.x);
            atomicAdd(&bsum[c * 4 + 1], s4.y); atomicAdd(&bsq[c * 4 + 1], q4.y);
            atomicAdd(&bsum[c * 4 + 2], s4.z); atomicAdd(&bsq[c * 4 + 2], q4.z);
            atomicAdd(&bsum[c * 4 + 3], s4.w); atomicAdd(&bsq[c * 4 + 3], q4.w);
        }
        __syncthreads();
        float* bank = g_bnpart[LIDX][blockIdx.x & (NBANK - 1)];
        for (int i = tid; i < FPAD; i += blockDim.x) {
            atomicAdd(&bank[i],      bsum[i]);
            atomicAdd(&bank[64 + i], bsq[i]);
        }
    }
}

// ------ register-tiled GEMM with inline BN-param computation ----------------
template<int FIN, int IS, int FOUT, int NC, int NG, int NT,
         int BNL, bool DINV_OUT, int IB, int OB>
__global__ void k_gemm(const float* __restrict__ W,
                       const float* __restrict__ gv,
                       const float* __restrict__ bev) {
    constexpr int NO   = 4;
    constexpr int NPB  = NG * NT;
    constexpr int SPAD = FIN + 4;
    constexpr bool BN_IN = (BNL >= 0);
    constexpr int BL = BN_IN ? BNL : 0;
    const float* __restrict__ in = buff<IB>();
    float* __restrict__ out = buff<OB>();
    __shared__ float sW[FIN * FOUT];
    __shared__ float sIn[NPB * SPAD];
    __shared__ float sbna[BN_IN ? FIN : 1];
    __shared__ float sbnc[BN_IN ? FIN : 1];
    const int tid = threadIdx.x;
    const int nthreads = NC * NG;
    for (int idx = tid; idx < FIN * FOUT / 4; idx += nthreads)
        reinterpret_cast<float4*>(sW)[idx] = reinterpret_cast<const float4*>(W)[idx];
    if (BN_IN && tid < FIN) {
        float sum = 0.f, sq = 0.f;
        #pragma unroll
        for (int b = 0; b < NBANK; b++) {
            sum += g_bnpart[BL][b][tid];
            sq  += g_bnpart[BL][b][64 + tid];
        }
        float inv_n = 1.0f / (float)N_NODES;
        float mu  = sum * inv_n;
        float var = sq * inv_n - mu * mu;
        float a = gv[tid] * rsqrtf(var + BN_EPS);
        sbna[tid] = a;
        sbnc[tid] = bev[tid] - mu * a;
    }
    const int co = tid % NC;
    const int g  = tid / NC;
    for (int base = blockIdx.x * NPB; base < N_NODES; base += gridDim.x * NPB) {
        __syncthreads();
        for (int idx = tid; idx < NPB * (FIN / 4); idx += nthreads) {
            int nl = idx / (FIN / 4), k4 = idx - nl * (FIN / 4);
            int node = base + nl;
            float4 v = {0.f, 0.f, 0.f, 0.f};
            if (node < N_NODES) {
                v = *reinterpret_cast<const float4*>(&in[node * IS + k4 * 4]);
                if (BN_IN) {
                    int k = k4 * 4;
                    v.x = fmaxf(fmaf(v.x, sbna[k],     sbnc[k]),     0.f);
                    v.y = fmaxf(fmaf(v.y, sbna[k + 1], sbnc[k + 1]), 0.f);
                    v.z = fmaxf(fmaf(v.z, sbna[k + 2], sbnc[k + 2]), 0.f);
                    v.w = fmaxf(fmaf(v.w, sbna[k + 3], sbnc[k + 3]), 0.f);
                }
            }
            *reinterpret_cast<float4*>(&sIn[nl * SPAD + k4 * 4]) = v;
        }
        __syncthreads();
        float acc[NT][NO];
        #pragma unroll
        for (int j = 0; j < NT; j++)
            #pragma unroll
            for (int o = 0; o < NO; o++) acc[j][o] = 0.f;
        #pragma unroll 2
        for (int k4 = 0; k4 < FIN / 4; k4++) {
            float4 a[NT];
            #pragma unroll
            for (int j = 0; j < NT; j++)
                a[j] = *reinterpret_cast<const float4*>(
                    &sIn[(g * NT + j) * SPAD + k4 * 4]);
            #pragma unroll
            for (int kk = 0; kk < 4; kk++) {
                float4 w = *reinterpret_cast<const float4*>(
                    &sW[(k4 * 4 + kk) * FOUT + co * NO]);
                #pragma unroll
                for (int j = 0; j < NT; j++) {
                    float av = (kk == 0) ? a[j].x : (kk == 1) ? a[j].y
                             : (kk == 2) ? a[j].z : a[j].w;
                    acc[j][0] = fmaf(av, w.x, acc[j][0]);
                    acc[j][1] = fmaf(av, w.y, acc[j][1]);
                    acc[j][2] = fmaf(av, w.z, acc[j][2]);
                    acc[j][3] = fmaf(av, w.w, acc[j][3]);
                }
            }
        }
        #pragma unroll
        for (int j = 0; j < NT; j++) {
            int node = base + g * NT + j;
            if (node < N_NODES) {
                float d = DINV_OUT ? g_dinv[node] : 1.f;
                float4 o = {acc[j][0] * d, acc[j][1] * d, acc[j][2] * d, acc[j][3] * d};
                *reinterpret_cast<float4*>(&out[node * FOUT + co * NO]) = o;
            }
        }
    }
}

// ------- final apply: out = bn3(b2 rows, stride 32), params inline ----------
__global__ void k_apply(const float* __restrict__ gv,
                        const float* __restrict__ bev,
                        float* __restrict__ out) {
    __shared__ float sa[32];
    __shared__ float sc[32];
    const int tid = threadIdx.x;
    if (tid < 32) {
        float sum = 0.f, sq = 0.f;
        #pragma unroll
        for (int b = 0; b < NBANK; b++) {
            sum += g_bnpart[2][b][tid];
            sq  += g_bnpart[2][b][64 + tid];
        }
        float inv_n = 1.0f / (float)N_NODES;
        float mu  = sum * inv_n;
        float var = sq * inv_n - mu * mu;
        float a = gv[tid] * rsqrtf(var + BN_EPS);
        sa[tid] = a;
        sc[tid] = bev[tid] - mu * a;
    }
    __syncthreads();
    const int total = N_NODES * 32;
    const int stride = gridDim.x * blockDim.x;
    for (int idx = blockIdx.x * blockDim.x + tid; idx < total; idx += stride) {
        int f = idx & 31;
        out[idx] = fmaf(((const float*)g_b2)[idx], sa[f], sc[f]);
    }
}

// ---------------- launcher ----------------
extern "C" void kernel_launch(void* const* d_in, const int* in_sizes, int n_in,
                              void* d_out, int out_size) {
    const float* x   = (const float*)d_in[0];
    const int*   ei  = (const int*)d_in[1];          // int32
    const float* W1  = (const float*)d_in[2];
    const float* g1  = (const float*)d_in[4];
    const float* be1 = (const float*)d_in[5];
    const float* W2  = (const float*)d_in[6];
    const float* g2  = (const float*)d_in[8];
    const float* be2 = (const float*)d_in[9];
    const float* W3  = (const float*)d_in[10];
    const float* g3  = (const float*)d_in[12];
    const float* be3 = (const float*)d_in[13];
    float* out = (float*)d_out;

    // zero per-call state (memset nodes, not kernel launches)
    void* pa;
    cudaGetSymbolAddress(&pa, g_count);
    cudaMemsetAsync(pa, 0, sizeof(int) * N_NODES);
    cudaGetSymbolAddress(&pa, g_bnpart);
    cudaMemsetAsync(pa, 0, sizeof(float) * 3 * NBANK * 128);

    // ---- build + prep ----
    k_scatter<<<(N_EDGES / 2 + 255) / 256, 256>>>(ei);        // 0
    k_prep<<<(N_NODES + 255) / 256, 256>>>(x);                // 1

    // ---- layer 1 fused: gather(20f) + GEMM 20->64 + BN1 stats ----
    k_layer1<<<2048, 256>>>(W1);                              // 2: b0 -> b2

    // ---- layer 2 ----
    k_gemm<64, 64, 48, 12, 20, 4, 0, true, 2, 0>
        <<<(N_NODES + 79) / 80, 240>>>(W2, g1, be1);          // 3 <- PROFILED: b2 -> b0
    k_gather<48, 2, 0, 1, 1><<<2048, 256>>>();                // 4: b0 -> b1 (+BN2 stats)

    // ---- layer 3 ----
    k_gemm<48, 48, 32, 8, 32, 4, 1, true, 1, 0>
        <<<(N_NODES + 127) / 128, 256>>>(W3, g2, be2);        // 5: b1 -> b0
    k_gather<32, 4, 0, 2, 2><<<2048, 256>>>();                // 6: b0 -> b2 (+BN3 stats)

    // ---- final BN apply (params inline) ----
    k_apply<<<2048, 256>>>(g3, be3, out);                     // 7
}